// round 1
// baseline (speedup 1.0000x reference)
#include <cuda_runtime.h>
#include <math.h>

// LSTM cell, fused:  gates = x@Wx + h@Wh + bx + bh ; standard LSTM gating.
// B=16384, IN=512, H=512, K_total = IN+H = 1024, gate matrix width 4H = 2048.
//
// Strategy (round 0 baseline):
//  - One 128x128x16 SMEM-tiled fp32 GEMM per CTA over the concatenated K.
//  - N-tile is gate-interleaved: n = gate*32 + (j - j0), so every thread's
//    8 output columns are {i,f,g,o} x {j, j+1} -> epilogue is thread-local.
//  - Epilogue applies bias + sigmoid/tanh gating and writes h_new, c_new
//    directly (no [B,4H] intermediate ever touches HBM).

#define BM 128
#define BK 16
#define BN 128
#define APAD 4

static constexpr int Bsz = 16384;
static constexpr int INF = 512;
static constexpr int Hd  = 512;
static constexpr int FH  = 2048;   // 4*H

__device__ __forceinline__ float sigmoidf_(float v) {
    return 1.0f / (1.0f + __expf(-v));
}

__global__ __launch_bounds__(256, 2)
void lstm_cell_kernel(const float* __restrict__ x,  const float* __restrict__ h,
                      const float* __restrict__ c,
                      const float* __restrict__ Wx, const float* __restrict__ Wh,
                      const float* __restrict__ bx, const float* __restrict__ bh,
                      float* __restrict__ out)
{
    __shared__ float As[BK][BM + APAD];  // A stored transposed: As[k][m]
    __shared__ float Bs[BK][BN];         // Bs[k][n], n = gate*32 + (j - j0)

    const int tid = threadIdx.x;
    const int tx  = tid & 15;            // 16 thread-cols
    const int ty  = tid >> 4;            // 16 thread-rows
    const int m0  = blockIdx.y * BM;     // batch tile origin
    const int j0  = blockIdx.x * 32;     // per-gate column tile origin

    float acc[8][8];                     // [row][gate*2 + jj]
    #pragma unroll
    for (int i = 0; i < 8; ++i)
        #pragma unroll
        for (int j = 0; j < 8; ++j) acc[i][j] = 0.0f;

    // A-load mapping: 128 rows x 16 cols, float4 per thread, 2 passes
    const int ar = tid >> 2;             // 0..63
    const int ac = (tid & 3) * 4;        // 0,4,8,12
    // B-load mapping: 16 rows x 128 gate-interleaved cols, float4, 2 passes
    const int bn4  = tid & 31;           // float4 index over the 128 n-cols
    const int brow = tid >> 5;           // 0..7
    const int bcol = (bn4 >> 3) * 512 + j0 + (bn4 & 7) * 4;  // gmem column

    for (int k0 = 0; k0 < INF + Hd; k0 += BK) {
        // K never straddles the x/h boundary (512 % 16 == 0): pointer-select.
        const float* Ap = (k0 < INF) ? (x  + (size_t)m0 * INF + k0)
                                     : (h  + (size_t)m0 * Hd  + (k0 - INF));
        const float* Wp = (k0 < INF) ? (Wx + (size_t)k0 * FH)
                                     : (Wh + (size_t)(k0 - INF) * FH);

        #pragma unroll
        for (int p = 0; p < 2; ++p) {
            float4 v = *reinterpret_cast<const float4*>(
                Ap + (size_t)(ar + p * 64) * 512 + ac);
            As[ac + 0][ar + p * 64] = v.x;
            As[ac + 1][ar + p * 64] = v.y;
            As[ac + 2][ar + p * 64] = v.z;
            As[ac + 3][ar + p * 64] = v.w;
        }
        #pragma unroll
        for (int p = 0; p < 2; ++p) {
            float4 v = *reinterpret_cast<const float4*>(
                Wp + (size_t)(brow + p * 8) * FH + bcol);
            *reinterpret_cast<float4*>(&Bs[brow + p * 8][bn4 * 4]) = v;
        }
        __syncthreads();

        #pragma unroll
        for (int k = 0; k < BK; ++k) {
            float a[8], b[8];
            float4 a0 = *reinterpret_cast<const float4*>(&As[k][ty * 4]);
            float4 a1 = *reinterpret_cast<const float4*>(&As[k][64 + ty * 4]);
            a[0] = a0.x; a[1] = a0.y; a[2] = a0.z; a[3] = a0.w;
            a[4] = a1.x; a[5] = a1.y; a[6] = a1.z; a[7] = a1.w;
            #pragma unroll
            for (int g = 0; g < 4; ++g) {
                float2 bv = *reinterpret_cast<const float2*>(
                    &Bs[k][g * 32 + tx * 2]);
                b[g * 2 + 0] = bv.x;
                b[g * 2 + 1] = bv.y;
            }
            #pragma unroll
            for (int i = 0; i < 8; ++i)
                #pragma unroll
                for (int j = 0; j < 8; ++j)
                    acc[i][j] = fmaf(a[i], b[j], acc[i][j]);
        }
        __syncthreads();
    }

    // ---- fused LSTM epilogue (all gates for a given j live in this thread) ----
    const int jA = j0 + tx * 2;          // first of this thread's two j-columns
    float bias[8];
    #pragma unroll
    for (int g = 0; g < 4; ++g)
        #pragma unroll
        for (int jj = 0; jj < 2; ++jj) {
            int colg = g * 512 + jA + jj;
            bias[g * 2 + jj] = bx[colg] + bh[colg];
        }

    float* outH = out;                          // h_new (first tuple element)
    float* outC = out + (size_t)Bsz * Hd;       // c_new (second tuple element)

    #pragma unroll
    for (int i = 0; i < 8; ++i) {
        int rg = m0 + ((i < 4) ? (ty * 4 + i) : (64 + ty * 4 + (i - 4)));
        float2 cold = *reinterpret_cast<const float2*>(
            c + (size_t)rg * Hd + jA);
        float2 hv, cv;
        #pragma unroll
        for (int jj = 0; jj < 2; ++jj) {
            float gi = acc[i][0 + jj] + bias[0 + jj];
            float gf = acc[i][2 + jj] + bias[2 + jj];
            float gg = acc[i][4 + jj] + bias[4 + jj];
            float go = acc[i][6 + jj] + bias[6 + jj];
            float ig = sigmoidf_(gi);
            float fg = sigmoidf_(gf);
            float g_ = tanhf(gg);
            float og = sigmoidf_(go);
            float co = (jj == 0) ? cold.x : cold.y;
            float cn = fg * co + ig * g_;
            float hn = og * tanhf(cn);
            if (jj == 0) { cv.x = cn; hv.x = hn; }
            else         { cv.y = cn; hv.y = hn; }
        }
        *reinterpret_cast<float2*>(outH + (size_t)rg * Hd + jA) = hv;
        *reinterpret_cast<float2*>(outC + (size_t)rg * Hd + jA) = cv;
    }
}

extern "C" void kernel_launch(void* const* d_in, const int* in_sizes, int n_in,
                              void* d_out, int out_size) {
    const float* x  = (const float*)d_in[0];
    const float* h  = (const float*)d_in[1];
    const float* c  = (const float*)d_in[2];
    const float* Wx = (const float*)d_in[3];
    const float* Wh = (const float*)d_in[4];
    const float* bx = (const float*)d_in[5];
    const float* bh = (const float*)d_in[6];
    float* out = (float*)d_out;

    dim3 grid(Hd / 32, Bsz / BM);   // (16, 128) = 2048 CTAs
    lstm_cell_kernel<<<grid, 256>>>(x, h, c, Wx, Wh, bx, bh, out);
}

// round 3
// speedup vs baseline: 1.8961x; 1.8961x over previous
#include <cuda_runtime.h>
#include <cstdint>

// LSTM cell: gates = [x|h] @ [Wx;Wh] + bx + bh, fused epilogue.
// B=16384, IN=H=512, K=1024, N=4H=2048.
// Tensor path: mma.sync m16n8k8 tf32 (arch-agnostic PTX; tcgen05 is not
// reachable through this toolchain's compute_103 virtual arch).
// Prepass transposes W into K-major, gate-interleaved (granularity 16) Bt,
// rounded to tf32. Main kernel: 128x256x32 CTA tile, 8 warps (2x4),
// warp tile 64x64, 3-stage cp.async pipeline, thread-local LSTM epilogue.

static constexpr int Bsz  = 16384;
static constexpr int INF  = 512;
static constexpr int Hd   = 512;
static constexpr int FH   = 2048;
static constexpr int Ktot = 1024;

#define BM 128
#define BN 256
#define BK 32
#define NSTAGE 3
#define NITER (Ktot / BK)          // 32
#define A_STRIDE 36                 // floats per SMEM row (pad 4: conflict-free)
#define B_STRIDE 36
#define A_STG (BM * A_STRIDE)       // 4608 floats
#define B_STG (BN * B_STRIDE)       // 9216 floats
#define STG   (A_STG + B_STG)       // 13824 floats per stage
#define SMEM_BYTES ((256 + NSTAGE * STG) * 4)   // 166912

__device__ float g_Bt[(size_t)FH * Ktot];       // 8 MB transposed tf32 weights

// ---------------- helpers ----------------
__device__ __forceinline__ uint32_t cvta_s(const void* p) {
    return (uint32_t)__cvta_generic_to_shared(p);
}
__device__ __forceinline__ void cpa16(uint32_t s, const void* g) {
    asm volatile("cp.async.cg.shared.global [%0], [%1], 16;"
                 :: "r"(s), "l"(g) : "memory");
}
__device__ __forceinline__ uint32_t tf32r(float f) {
    uint32_t u;
    asm("cvt.rna.tf32.f32 %0, %1;" : "=r"(u) : "f"(f));
    return u;
}
__device__ __forceinline__ void mma8(float* d, const uint32_t* a, const uint32_t* b) {
    asm volatile(
        "mma.sync.aligned.m16n8k8.row.col.f32.tf32.tf32.f32 "
        "{%0,%1,%2,%3}, {%4,%5,%6,%7}, {%8,%9}, {%0,%1,%2,%3};"
        : "+f"(d[0]), "+f"(d[1]), "+f"(d[2]), "+f"(d[3])
        : "r"(a[0]), "r"(a[1]), "r"(a[2]), "r"(a[3]), "r"(b[0]), "r"(b[1]));
}
__device__ __forceinline__ float rcp_(float a) {
    float r; asm("rcp.approx.f32 %0, %1;" : "=f"(r) : "f"(a)); return r;
}
__device__ __forceinline__ float sigm_(float v) { return rcp_(1.0f + __expf(-v)); }
__device__ __forceinline__ float tanh_(float v) {
    return 2.0f * rcp_(1.0f + __expf(-2.0f * v)) - 1.0f;
}

// -------- prepass: W[k][gate*512+j] -> Bt[(j>>4)*64+gate*16+(j&15)][k], tf32 ----
__global__ void prep_Bt(const float* __restrict__ Wx, const float* __restrict__ Wh) {
    __shared__ float t[32][33];
    const int k0 = blockIdx.x * 32;
    const int n0 = blockIdx.y * 32;                 // one gate per tile
    const float* W = (k0 < INF) ? (Wx + (size_t)k0 * FH)
                                : (Wh + (size_t)(k0 - INF) * FH);
    const int tx = threadIdx.x, ty = threadIdx.y;
    #pragma unroll
    for (int i = 0; i < 4; ++i) {
        int kk = ty + i * 8;
        t[kk][tx] = W[(size_t)kk * FH + n0 + tx];
    }
    __syncthreads();
    const int gate = n0 >> 9;
    const int j0   = n0 & 511;
    #pragma unroll
    for (int i = 0; i < 4; ++i) {
        int nn = ty + i * 8;
        int j  = j0 + nn;
        int np = ((j >> 4) << 6) + gate * 16 + (j & 15);
        g_Bt[(size_t)np * Ktot + k0 + tx] = __uint_as_float(tf32r(t[tx][nn]));
    }
}

// ---------------- main GEMM + LSTM epilogue ----------------
__global__ __launch_bounds__(256, 1)
void lstm_mma(const float* __restrict__ x, const float* __restrict__ h,
              const float* __restrict__ c,
              const float* __restrict__ bx, const float* __restrict__ bh,
              float* __restrict__ out)
{
    extern __shared__ float sm[];
    float* biasS = sm;                      // 256 floats: [gate][64 j]
    float* stg0  = sm + 256;

    const int tid  = threadIdx.x;
    const int lane = tid & 31;
    const int wid  = tid >> 5;
    const int wm   = wid >> 2;              // 0..1
    const int wn   = wid & 3;               // 0..3
    const int m0   = blockIdx.y * BM;
    const int n0   = blockIdx.x * BN;
    const int jb   = blockIdx.x * 64;       // 64 hidden cols per CTA

    {   // bias = bx + bh, gate-major
        int g = tid >> 6, jj = tid & 63;
        int colg = g * 512 + jb + jj;
        biasS[tid] = bx[colg] + bh[colg];
    }

    float acc[4][8][4];
    #pragma unroll
    for (int a = 0; a < 4; ++a)
        #pragma unroll
        for (int b = 0; b < 8; ++b)
            #pragma unroll
            for (int d = 0; d < 4; ++d) acc[a][b][d] = 0.0f;

    auto load_stage = [&](int s, int kc) {
        const int k0 = kc * BK;
        float* As = stg0 + s * STG;
        float* Bs = As + A_STG;
        const float* Ap = (k0 < INF) ? (x + (size_t)m0 * 512 + k0)
                                     : (h + (size_t)m0 * 512 + (k0 - INF));
        #pragma unroll
        for (int p = 0; p < 4; ++p) {
            int q = tid + 256 * p, row = q >> 3, c4 = (q & 7) * 4;
            cpa16(cvta_s(As + row * A_STRIDE + c4),
                  Ap + (size_t)row * 512 + c4);
        }
        const float* Bp = g_Bt + (size_t)n0 * Ktot + k0;
        #pragma unroll
        for (int p = 0; p < 8; ++p) {
            int q = tid + 256 * p, row = q >> 3, c4 = (q & 7) * 4;
            cpa16(cvta_s(Bs + row * B_STRIDE + c4),
                  Bp + (size_t)row * Ktot + c4);
        }
        asm volatile("cp.async.commit_group;" ::: "memory");
    };

    load_stage(0, 0);
    load_stage(1, 1);

    for (int it = 0; it < NITER; ++it) {
        asm volatile("cp.async.wait_group 1;" ::: "memory");
        __syncthreads();
        if (it + 2 < NITER) load_stage((it + 2) % NSTAGE, it + 2);
        else asm volatile("cp.async.commit_group;" ::: "memory");

        const float* As = stg0 + (it % NSTAGE) * STG;
        const float* Bs = As + A_STG;

        #pragma unroll
        for (int ks = 0; ks < 4; ++ks) {
            const int kb = ks * 8;
            uint32_t afr[4][4], bfr[8][2];
            #pragma unroll
            for (int mf = 0; mf < 4; ++mf) {
                int r0 = wm * 64 + mf * 16 + (lane >> 2);
                afr[mf][0] = tf32r(As[r0 * A_STRIDE + kb + (lane & 3)]);
                afr[mf][1] = tf32r(As[(r0 + 8) * A_STRIDE + kb + (lane & 3)]);
                afr[mf][2] = tf32r(As[r0 * A_STRIDE + kb + 4 + (lane & 3)]);
                afr[mf][3] = tf32r(As[(r0 + 8) * A_STRIDE + kb + 4 + (lane & 3)]);
            }
            #pragma unroll
            for (int nf = 0; nf < 8; ++nf) {
                int nr = wn * 64 + nf * 8 + (lane >> 2);
                bfr[nf][0] = __float_as_uint(Bs[nr * B_STRIDE + kb + (lane & 3)]);
                bfr[nf][1] = __float_as_uint(Bs[nr * B_STRIDE + kb + 4 + (lane & 3)]);
            }
            #pragma unroll
            for (int mf = 0; mf < 4; ++mf)
                #pragma unroll
                for (int nf = 0; nf < 8; ++nf)
                    mma8(acc[mf][nf], afr[mf], bfr[nf]);
        }
        __syncthreads();
    }

    // ---- fused LSTM epilogue (thread-local: all 4 gates per j in-registers) ----
    const size_t HC = (size_t)Bsz * Hd;
    #pragma unroll
    for (int mf = 0; mf < 4; ++mf) {
        #pragma unroll
        for (int e = 0; e < 2; ++e) {
            size_t row = (size_t)m0 + wm * 64 + mf * 16 + (lane >> 2) + e * 8;
            #pragma unroll
            for (int half = 0; half < 2; ++half) {
                int q  = 2 * (lane & 3) + half * 8;   // j within warp's 16
                int bq = wn * 16 + q;                 // j within CTA's 64
                int j  = jb + bq;                     // global hidden index
                float2 cold = *reinterpret_cast<const float2*>(c + row * 512 + j);
                float hv[2], cv[2];
                #pragma unroll
                for (int d = 0; d < 2; ++d) {
                    float gi = acc[mf][0 + half][e * 2 + d] + biasS[      bq + d];
                    float gf = acc[mf][2 + half][e * 2 + d] + biasS[ 64 + bq + d];
                    float gg = acc[mf][4 + half][e * 2 + d] + biasS[128 + bq + d];
                    float go = acc[mf][6 + half][e * 2 + d] + biasS[192 + bq + d];
                    float i_ = sigm_(gi), f_ = sigm_(gf);
                    float g_ = tanh_(gg), o_ = sigm_(go);
                    float co = d ? cold.y : cold.x;
                    float cn = f_ * co + i_ * g_;
                    cv[d] = cn;
                    hv[d] = o_ * tanh_(cn);
                }
                *reinterpret_cast<float2*>(out + row * 512 + j) =
                    make_float2(hv[0], hv[1]);
                *reinterpret_cast<float2*>(out + HC + row * 512 + j) =
                    make_float2(cv[0], cv[1]);
            }
        }
    }
}

extern "C" void kernel_launch(void* const* d_in, const int* in_sizes, int n_in,
                              void* d_out, int out_size) {
    const float* x  = (const float*)d_in[0];
    const float* h  = (const float*)d_in[1];
    const float* c  = (const float*)d_in[2];
    const float* Wx = (const float*)d_in[3];
    const float* Wh = (const float*)d_in[4];
    const float* bx = (const float*)d_in[5];
    const float* bh = (const float*)d_in[6];
    float* out = (float*)d_out;

    static bool attr_set = false;
    if (!attr_set) {
        cudaFuncSetAttribute(lstm_mma,
                             cudaFuncAttributeMaxDynamicSharedMemorySize,
                             SMEM_BYTES);
        attr_set = true;
    }

    prep_Bt<<<dim3(Ktot / 32, FH / 32), dim3(32, 8)>>>(Wx, Wh);
    lstm_mma<<<dim3(FH / BN, Bsz / BM), 256, SMEM_BYTES>>>(x, h, c, bx, bh, out);
}

// round 4
// speedup vs baseline: 4.5325x; 2.3905x over previous
#include <cuda_runtime.h>
#include <cuda_fp16.h>
#include <cstdint>

// LSTM cell: gates = [x|h] @ [Wx;Wh] + bx + bh, fused epilogue.
// B=16384, IN=H=512, K=1024, N=4H=2048.
// Round 4: fp16 mma.sync m16n8k16 (f32 accum) + ldmatrix fragments.
// Prepass converts A=[x|h] and gate-interleaved K-major W to fp16 once.

static constexpr int Bsz  = 16384;
static constexpr int INF  = 512;
static constexpr int Hd   = 512;
static constexpr int FH   = 2048;
static constexpr int Ktot = 1024;

#define BM 128
#define BN 256
#define BK 32
#define NSTAGE 4
#define NITER (Ktot / BK)              // 32
#define ROWSTR 40                      // halves per SMEM row (80 B) - conflict-free
#define A_STG_B (BM * ROWSTR * 2)      // 10240 B
#define B_STG_B (BN * ROWSTR * 2)      // 20480 B
#define STG_B   (A_STG_B + B_STG_B)    // 30720 B
#define SMEM_BYTES (1024 + NSTAGE * STG_B)   // 123904

__device__ __half g_A16[(size_t)Bsz * Ktot];   // 32 MB  [b][k]  (x | h)
__device__ __half g_Bt16[(size_t)FH * Ktot];   // 4 MB   [n'][k] gate-interleaved

// ---------------- helpers ----------------
__device__ __forceinline__ uint32_t cvta_s(const void* p) {
    return (uint32_t)__cvta_generic_to_shared(p);
}
__device__ __forceinline__ void cpa16(uint32_t s, const void* g) {
    asm volatile("cp.async.cg.shared.global [%0], [%1], 16;"
                 :: "r"(s), "l"(g) : "memory");
}
__device__ __forceinline__ void ldm4(uint32_t* r, uint32_t a) {
    asm volatile("ldmatrix.sync.aligned.m8n8.x4.shared.b16 {%0,%1,%2,%3}, [%4];"
                 : "=r"(r[0]), "=r"(r[1]), "=r"(r[2]), "=r"(r[3]) : "r"(a));
}
__device__ __forceinline__ void mma16(float* d, const uint32_t* a, const uint32_t* b) {
    asm volatile(
        "mma.sync.aligned.m16n8k16.row.col.f32.f16.f16.f32 "
        "{%0,%1,%2,%3}, {%4,%5,%6,%7}, {%8,%9}, {%0,%1,%2,%3};"
        : "+f"(d[0]), "+f"(d[1]), "+f"(d[2]), "+f"(d[3])
        : "r"(a[0]), "r"(a[1]), "r"(a[2]), "r"(a[3]), "r"(b[0]), "r"(b[1]));
}
__device__ __forceinline__ float rcp_(float a) {
    float r; asm("rcp.approx.f32 %0, %1;" : "=f"(r) : "f"(a)); return r;
}
__device__ __forceinline__ float sigm_(float v) { return rcp_(1.0f + __expf(-v)); }
__device__ __forceinline__ float tanh_(float v) {
    return 2.0f * rcp_(1.0f + __expf(-2.0f * v)) - 1.0f;
}

// -------- prepass 1: [x|h] -> g_A16 fp16 --------
__global__ void prep_A(const float* __restrict__ x, const float* __restrict__ h) {
    size_t idx = (size_t)blockIdx.x * blockDim.x + threadIdx.x;   // float4 id
    const size_t NQ = (size_t)Bsz * INF / 4;                      // per stream
    if (idx < NQ) {
        size_t b = idx >> 7, c4 = (idx & 127) * 4;
        float4 v = *reinterpret_cast<const float4*>(x + b * INF + c4);
        __half2 lo = __floats2half2_rn(v.x, v.y);
        __half2 hi = __floats2half2_rn(v.z, v.w);
        *reinterpret_cast<__half2*>(g_A16 + b * Ktot + c4)     = lo;
        *reinterpret_cast<__half2*>(g_A16 + b * Ktot + c4 + 2) = hi;
    } else if (idx < 2 * NQ) {
        size_t q = idx - NQ;
        size_t b = q >> 7, c4 = (q & 127) * 4;
        float4 v = *reinterpret_cast<const float4*>(h + b * Hd + c4);
        __half2 lo = __floats2half2_rn(v.x, v.y);
        __half2 hi = __floats2half2_rn(v.z, v.w);
        *reinterpret_cast<__half2*>(g_A16 + b * Ktot + 512 + c4)     = lo;
        *reinterpret_cast<__half2*>(g_A16 + b * Ktot + 512 + c4 + 2) = hi;
    }
}

// -------- prepass 2: W[k][gate*512+j] -> g_Bt16[(j>>4)*64+gate*16+(j&15)][k] ----
__global__ void prep_Bt(const float* __restrict__ Wx, const float* __restrict__ Wh) {
    __shared__ float t[32][33];
    const int k0 = blockIdx.x * 32;
    const int n0 = blockIdx.y * 32;                 // one gate per tile
    const float* W = (k0 < INF) ? (Wx + (size_t)k0 * FH)
                                : (Wh + (size_t)(k0 - INF) * FH);
    const int tx = threadIdx.x, ty = threadIdx.y;
    #pragma unroll
    for (int i = 0; i < 4; ++i) {
        int kk = ty + i * 8;
        t[kk][tx] = W[(size_t)kk * FH + n0 + tx];
    }
    __syncthreads();
    const int gate = n0 >> 9;
    const int j0   = n0 & 511;
    #pragma unroll
    for (int i = 0; i < 4; ++i) {
        int nn = ty + i * 8;
        int j  = j0 + nn;
        int np = ((j >> 4) << 6) + gate * 16 + (j & 15);
        g_Bt16[(size_t)np * Ktot + k0 + tx] = __float2half_rn(t[tx][nn]);
    }
}

// ---------------- main GEMM + LSTM epilogue ----------------
__global__ __launch_bounds__(256, 1)
void lstm_mma(const float* __restrict__ c,
              const float* __restrict__ bx, const float* __restrict__ bh,
              float* __restrict__ out)
{
    extern __shared__ char smraw[];
    float* biasS = reinterpret_cast<float*>(smraw);        // 256 floats
    char*  stg0  = smraw + 1024;

    const int tid  = threadIdx.x;
    const int lane = tid & 31;
    const int wid  = tid >> 5;
    const int wm   = wid >> 2;              // 0..1
    const int wn   = wid & 3;               // 0..3
    const int m0   = blockIdx.y * BM;
    const int n0   = blockIdx.x * BN;
    const int jb   = blockIdx.x * 64;

    {   // bias = bx + bh, gate-major [gate][64 j]
        int g = tid >> 6, jj = tid & 63;
        int colg = g * 512 + jb + jj;
        biasS[tid] = bx[colg] + bh[colg];
    }

    float acc[4][8][4];
    #pragma unroll
    for (int a = 0; a < 4; ++a)
        #pragma unroll
        for (int b = 0; b < 8; ++b)
            #pragma unroll
            for (int d = 0; d < 4; ++d) acc[a][b][d] = 0.0f;

    // ldmatrix per-lane geometry
    const int grp = lane >> 3, gi = lane & 7;
    // A: matrices {m-lo,k-lo},{m-hi,k-lo},{m-lo,k-hi},{m-hi,k-hi}
    const int a_row  = wm * 64 + (grp & 1) * 8 + gi;
    const int a_kofs = (grp >> 1) * 8;
    const uint32_t a_base = (uint32_t)(a_row * ROWSTR + a_kofs) * 2;
    // B: matrices {n-lo,k-lo},{n-lo,k-hi},{n-hi,k-lo},{n-hi,k-hi}
    const int b_row  = wn * 64 + (grp >> 1) * 8 + gi;
    const int b_kofs = (grp & 1) * 8;
    const uint32_t b_base = (uint32_t)(b_row * ROWSTR + b_kofs) * 2;

    // cp.async geometry: A 2 chunks/thread, B 4 chunks/thread (16B each)
    auto load_stage = [&](int s, int kc) {
        const int k0 = kc * BK;
        char* As = stg0 + s * STG_B;
        char* Bs = As + A_STG_B;
        const __half* Ap = g_A16 + (size_t)m0 * Ktot + k0;
        #pragma unroll
        for (int p = 0; p < 2; ++p) {
            int q = tid + 256 * p, row = q >> 2, c8 = (q & 3) * 8;
            cpa16(cvta_s(As + (row * ROWSTR + c8) * 2),
                  Ap + (size_t)row * Ktot + c8);
        }
        const __half* Bp = g_Bt16 + (size_t)n0 * Ktot + k0;
        #pragma unroll
        for (int p = 0; p < 4; ++p) {
            int q = tid + 256 * p, row = q >> 2, c8 = (q & 3) * 8;
            cpa16(cvta_s(Bs + (row * ROWSTR + c8) * 2),
                  Bp + (size_t)row * Ktot + c8);
        }
        asm volatile("cp.async.commit_group;" ::: "memory");
    };

    load_stage(0, 0);
    load_stage(1, 1);
    load_stage(2, 2);

    for (int it = 0; it < NITER; ++it) {
        asm volatile("cp.async.wait_group 2;" ::: "memory");
        __syncthreads();
        if (it + 3 < NITER) load_stage((it + 3) % NSTAGE, it + 3);
        else asm volatile("cp.async.commit_group;" ::: "memory");

        const uint32_t sA = cvta_s(stg0 + (it % NSTAGE) * STG_B);
        const uint32_t sB = sA + A_STG_B;

        #pragma unroll
        for (int ks = 0; ks < 2; ++ks) {             // two k16 steps per stage
            uint32_t afr[4][4], bfr[4][4];
            #pragma unroll
            for (int mf = 0; mf < 4; ++mf)
                ldm4(afr[mf], sA + a_base + mf * (16 * ROWSTR * 2) + ks * 32);
            #pragma unroll
            for (int np = 0; np < 4; ++np)
                ldm4(bfr[np], sB + b_base + np * (16 * ROWSTR * 2) + ks * 32);
            #pragma unroll
            for (int mf = 0; mf < 4; ++mf)
                #pragma unroll
                for (int np = 0; np < 4; ++np) {
                    mma16(acc[mf][np * 2 + 0], afr[mf], &bfr[np][0]);
                    mma16(acc[mf][np * 2 + 1], afr[mf], &bfr[np][2]);
                }
        }
        __syncthreads();
    }

    // ---- fused LSTM epilogue (thread-local: all 4 gates per j) ----
    const size_t HC = (size_t)Bsz * Hd;
    #pragma unroll
    for (int mf = 0; mf < 4; ++mf) {
        #pragma unroll
        for (int e = 0; e < 2; ++e) {
            size_t row = (size_t)m0 + wm * 64 + mf * 16 + (lane >> 2) + e * 8;
            #pragma unroll
            for (int half = 0; half < 2; ++half) {
                int q  = 2 * (lane & 3) + half * 8;   // j within warp's 16
                int bq = wn * 16 + q;                 // j within CTA's 64
                int j  = jb + bq;
                float2 cold = *reinterpret_cast<const float2*>(c + row * 512 + j);
                float hv[2], cv[2];
                #pragma unroll
                for (int d = 0; d < 2; ++d) {
                    float gi = acc[mf][0 + half][e * 2 + d] + biasS[      bq + d];
                    float gf = acc[mf][2 + half][e * 2 + d] + biasS[ 64 + bq + d];
                    float gg = acc[mf][4 + half][e * 2 + d] + biasS[128 + bq + d];
                    float go = acc[mf][6 + half][e * 2 + d] + biasS[192 + bq + d];
                    float i_ = sigm_(gi), f_ = sigm_(gf);
                    float g_ = tanh_(gg), o_ = sigm_(go);
                    float co = d ? cold.y : cold.x;
                    float cn = f_ * co + i_ * g_;
                    cv[d] = cn;
                    hv[d] = o_ * tanh_(cn);
                }
                *reinterpret_cast<float2*>(out + row * 512 + j) =
                    make_float2(hv[0], hv[1]);
                *reinterpret_cast<float2*>(out + HC + row * 512 + j) =
                    make_float2(cv[0], cv[1]);
            }
        }
    }
}

extern "C" void kernel_launch(void* const* d_in, const int* in_sizes, int n_in,
                              void* d_out, int out_size) {
    const float* x  = (const float*)d_in[0];
    const float* h  = (const float*)d_in[1];
    const float* c  = (const float*)d_in[2];
    const float* Wx = (const float*)d_in[3];
    const float* Wh = (const float*)d_in[4];
    const float* bx = (const float*)d_in[5];
    const float* bh = (const float*)d_in[6];
    float* out = (float*)d_out;

    static bool attr_set = false;
    if (!attr_set) {
        cudaFuncSetAttribute(lstm_mma,
                             cudaFuncAttributeMaxDynamicSharedMemorySize,
                             SMEM_BYTES);
        attr_set = true;
    }

    {   // prepass 1: x,h -> fp16 concatenated A
        size_t nthr = (size_t)Bsz * INF / 4 * 2;     // 4M threads
        prep_A<<<(unsigned)((nthr + 255) / 256), 256>>>(x, h);
    }
    prep_Bt<<<dim3(Ktot / 32, FH / 32), dim3(32, 8)>>>(Wx, Wh);
    lstm_mma<<<dim3(FH / BN, Bsz / BM), 256, SMEM_BYTES>>>(c, bx, bh, out);
}

// round 6
// speedup vs baseline: 5.0387x; 1.1117x over previous
#include <cuda_runtime.h>
#include <cuda_fp16.h>
#include <cstdint>

// LSTM cell: gates = [x|h] @ [Wx;Wh] + bx + bh, fused epilogue.
// B=16384, IN=H=512, K=1024, N=4H=2048.
// Round 6 (= R5 theory, compile fix): fp16 mma m16n8k16 + ldmatrix; BK=64
// stages (fewer barriers), fragment double-buffering to hide ldmatrix
// latency, 144B conflict-free rows.

static constexpr int Bsz  = 16384;
static constexpr int INF  = 512;
static constexpr int Hd   = 512;
static constexpr int FH   = 2048;
static constexpr int Ktot = 1024;

#define BM 128
#define BN 256
#define BK 64
#define NSTAGE 3
#define NITER (Ktot / BK)              // 16
#define ROWSTR 72                      // halves per SMEM row (144 B)
#define A_STG_B (BM * ROWSTR * 2)      // 18432 B
#define B_STG_B (BN * ROWSTR * 2)      // 36864 B
#define STG_B   (A_STG_B + B_STG_B)    // 55296 B
#define SMEM_BYTES (1024 + NSTAGE * STG_B)   // 166912

__device__ __half g_A16[(size_t)Bsz * Ktot];   // 32 MB  [b][k]  (x | h)
__device__ __half g_Bt16[(size_t)FH * Ktot];   // 4 MB   [n'][k] gate-interleaved

// ---------------- helpers ----------------
__device__ __forceinline__ uint32_t cvta_s(const void* p) {
    return (uint32_t)__cvta_generic_to_shared(p);
}
__device__ __forceinline__ void cpa16(uint32_t s, const void* g) {
    asm volatile("cp.async.cg.shared.global [%0], [%1], 16;"
                 :: "r"(s), "l"(g) : "memory");
}
__device__ __forceinline__ void ldm4(uint32_t* r, uint32_t a) {
    asm volatile("ldmatrix.sync.aligned.m8n8.x4.shared.b16 {%0,%1,%2,%3}, [%4];"
                 : "=r"(r[0]), "=r"(r[1]), "=r"(r[2]), "=r"(r[3]) : "r"(a));
}
__device__ __forceinline__ void mma16(float* d, const uint32_t* a, const uint32_t* b) {
    asm volatile(
        "mma.sync.aligned.m16n8k16.row.col.f32.f16.f16.f32 "
        "{%0,%1,%2,%3}, {%4,%5,%6,%7}, {%8,%9}, {%0,%1,%2,%3};"
        : "+f"(d[0]), "+f"(d[1]), "+f"(d[2]), "+f"(d[3])
        : "r"(a[0]), "r"(a[1]), "r"(a[2]), "r"(a[3]), "r"(b[0]), "r"(b[1]));
}
__device__ __forceinline__ float rcp_(float a) {
    float r; asm("rcp.approx.f32 %0, %1;" : "=f"(r) : "f"(a)); return r;
}
__device__ __forceinline__ float sigm_(float v) { return rcp_(1.0f + __expf(-v)); }
__device__ __forceinline__ float tanh_(float v) {
    return 2.0f * rcp_(1.0f + __expf(-2.0f * v)) - 1.0f;
}

// pack 4 floats -> 4 fp16 in one 8-byte value
__device__ __forceinline__ uint2 pack4h(float a, float b, float cc, float d) {
    __half2 lo = __floats2half2_rn(a, b);
    __half2 hi = __floats2half2_rn(cc, d);
    union { __half2 h2[2]; uint2 u; } u;
    u.h2[0] = lo;
    u.h2[1] = hi;
    return u.u;
}

// -------- prepass 1: [x|h] -> g_A16 fp16 --------
__global__ void prep_A(const float* __restrict__ x, const float* __restrict__ h) {
    size_t idx = (size_t)blockIdx.x * blockDim.x + threadIdx.x;   // float4 id
    const size_t NQ = (size_t)Bsz * INF / 4;                      // per stream
    if (idx < NQ) {
        size_t b = idx >> 7, c4 = (idx & 127) * 4;
        float4 v = *reinterpret_cast<const float4*>(x + b * INF + c4);
        *reinterpret_cast<uint2*>(g_A16 + b * Ktot + c4) =
            pack4h(v.x, v.y, v.z, v.w);
    } else if (idx < 2 * NQ) {
        size_t q = idx - NQ;
        size_t b = q >> 7, c4 = (q & 127) * 4;
        float4 v = *reinterpret_cast<const float4*>(h + b * Hd + c4);
        *reinterpret_cast<uint2*>(g_A16 + b * Ktot + 512 + c4) =
            pack4h(v.x, v.y, v.z, v.w);
    }
}

// -------- prepass 2: W[k][gate*512+j] -> g_Bt16[(j>>4)*64+gate*16+(j&15)][k] ----
__global__ void prep_Bt(const float* __restrict__ Wx, const float* __restrict__ Wh) {
    __shared__ float t[32][33];
    const int k0 = blockIdx.x * 32;
    const int n0 = blockIdx.y * 32;                 // one gate per tile
    const float* W = (k0 < INF) ? (Wx + (size_t)k0 * FH)
                                : (Wh + (size_t)(k0 - INF) * FH);
    const int tx = threadIdx.x, ty = threadIdx.y;
    #pragma unroll
    for (int i = 0; i < 4; ++i) {
        int kk = ty + i * 8;
        t[kk][tx] = W[(size_t)kk * FH + n0 + tx];
    }
    __syncthreads();
    const int gate = n0 >> 9;
    const int j0   = n0 & 511;
    #pragma unroll
    for (int i = 0; i < 4; ++i) {
        int nn = ty + i * 8;
        int j  = j0 + nn;
        int np = ((j >> 4) << 6) + gate * 16 + (j & 15);
        g_Bt16[(size_t)np * Ktot + k0 + tx] = __float2half_rn(t[tx][nn]);
    }
}

// ---------------- main GEMM + LSTM epilogue ----------------
__global__ __launch_bounds__(256, 1)
void lstm_mma(const float* __restrict__ c,
              const float* __restrict__ bx, const float* __restrict__ bh,
              float* __restrict__ out)
{
    extern __shared__ char smraw[];
    float* biasS = reinterpret_cast<float*>(smraw);        // 256 floats
    char*  stg0  = smraw + 1024;

    const int tid  = threadIdx.x;
    const int lane = tid & 31;
    const int wid  = tid >> 5;
    const int wm   = wid >> 2;              // 0..1
    const int wn   = wid & 3;               // 0..3
    const int m0   = blockIdx.y * BM;
    const int n0   = blockIdx.x * BN;
    const int jb   = blockIdx.x * 64;

    {   // bias = bx + bh, gate-major [gate][64 j]
        int g = tid >> 6, jj = tid & 63;
        int colg = g * 512 + jb + jj;
        biasS[tid] = bx[colg] + bh[colg];
    }

    float acc[4][8][4];
    #pragma unroll
    for (int a = 0; a < 4; ++a)
        #pragma unroll
        for (int b = 0; b < 8; ++b)
            #pragma unroll
            for (int d = 0; d < 4; ++d) acc[a][b][d] = 0.0f;

    // ldmatrix per-lane geometry
    const int grp = lane >> 3, gi = lane & 7;
    // A: matrices {m-lo,k-lo},{m-hi,k-lo},{m-lo,k-hi},{m-hi,k-hi}
    const int a_row  = wm * 64 + (grp & 1) * 8 + gi;
    const int a_kofs = (grp >> 1) * 8;
    const uint32_t a_base = (uint32_t)(a_row * ROWSTR + a_kofs) * 2;
    // B: matrices {n-lo,k-lo},{n-lo,k-hi},{n-hi,k-lo},{n-hi,k-hi}
    const int b_row  = wn * 64 + (grp >> 1) * 8 + gi;
    const int b_kofs = (grp & 1) * 8;
    const uint32_t b_base = (uint32_t)(b_row * ROWSTR + b_kofs) * 2;

    // cp.async geometry: BK=64 -> A 4 chunks/thread, B 8 chunks/thread (16B)
    auto load_stage = [&](int s, int kc) {
        const int k0 = kc * BK;
        char* As = stg0 + s * STG_B;
        char* Bs = As + A_STG_B;
        const __half* Ap = g_A16 + (size_t)m0 * Ktot + k0;
        #pragma unroll
        for (int p = 0; p < 4; ++p) {
            int q = tid + 256 * p, row = q >> 3, c8 = (q & 7) * 8;
            cpa16(cvta_s(As + (row * ROWSTR + c8) * 2),
                  Ap + (size_t)row * Ktot + c8);
        }
        const __half* Bp = g_Bt16 + (size_t)n0 * Ktot + k0;
        #pragma unroll
        for (int p = 0; p < 8; ++p) {
            int q = tid + 256 * p, row = q >> 3, c8 = (q & 7) * 8;
            cpa16(cvta_s(Bs + (row * ROWSTR + c8) * 2),
                  Bp + (size_t)row * Ktot + c8);
        }
        asm volatile("cp.async.commit_group;" ::: "memory");
    };

    load_stage(0, 0);
    load_stage(1, 1);

    uint32_t afr[2][4][4], bfr[2][4][4];

    for (int it = 0; it < NITER; ++it) {
        asm volatile("cp.async.wait_group 1;" ::: "memory");
        __syncthreads();
        if (it + 2 < NITER) load_stage((it + 2) % NSTAGE, it + 2);
        else asm volatile("cp.async.commit_group;" ::: "memory");

        const uint32_t sA = cvta_s(stg0 + (it % NSTAGE) * STG_B);
        const uint32_t sB = sA + A_STG_B;

        // preload fragments for ks=0
        #pragma unroll
        for (int mf = 0; mf < 4; ++mf)
            ldm4(afr[0][mf], sA + a_base + mf * (16 * ROWSTR * 2));
        #pragma unroll
        for (int np = 0; np < 4; ++np)
            ldm4(bfr[0][np], sB + b_base + np * (16 * ROWSTR * 2));

        #pragma unroll
        for (int ks = 0; ks < 4; ++ks) {             // four k16 steps per stage
            const int cur = ks & 1;
            if (ks < 3) {                            // prefetch next k16 frags
                const int nxt = cur ^ 1;
                #pragma unroll
                for (int mf = 0; mf < 4; ++mf)
                    ldm4(afr[nxt][mf],
                         sA + a_base + mf * (16 * ROWSTR * 2) + (ks + 1) * 32);
                #pragma unroll
                for (int np = 0; np < 4; ++np)
                    ldm4(bfr[nxt][np],
                         sB + b_base + np * (16 * ROWSTR * 2) + (ks + 1) * 32);
            }
            #pragma unroll
            for (int mf = 0; mf < 4; ++mf)
                #pragma unroll
                for (int np = 0; np < 4; ++np) {
                    mma16(acc[mf][np * 2 + 0], afr[cur][mf], &bfr[cur][np][0]);
                    mma16(acc[mf][np * 2 + 1], afr[cur][mf], &bfr[cur][np][2]);
                }
        }
        __syncthreads();
    }

    // ---- fused LSTM epilogue (thread-local: all 4 gates per j) ----
    const size_t HC = (size_t)Bsz * Hd;
    #pragma unroll
    for (int mf = 0; mf < 4; ++mf) {
        #pragma unroll
        for (int e = 0; e < 2; ++e) {
            size_t row = (size_t)m0 + wm * 64 + mf * 16 + (lane >> 2) + e * 8;
            #pragma unroll
            for (int half = 0; half < 2; ++half) {
                int q  = 2 * (lane & 3) + half * 8;   // j within warp's 16
                int bq = wn * 16 + q;                 // j within CTA's 64
                int j  = jb + bq;
                float2 cold = *reinterpret_cast<const float2*>(c + row * 512 + j);
                float hv[2], cv[2];
                #pragma unroll
                for (int d = 0; d < 2; ++d) {
                    float gi = acc[mf][0 + half][e * 2 + d] + biasS[      bq + d];
                    float gf = acc[mf][2 + half][e * 2 + d] + biasS[ 64 + bq + d];
                    float gg = acc[mf][4 + half][e * 2 + d] + biasS[128 + bq + d];
                    float go = acc[mf][6 + half][e * 2 + d] + biasS[192 + bq + d];
                    float i_ = sigm_(gi), f_ = sigm_(gf);
                    float g_ = tanh_(gg), o_ = sigm_(go);
                    float co = d ? cold.y : cold.x;
                    float cn = f_ * co + i_ * g_;
                    cv[d] = cn;
                    hv[d] = o_ * tanh_(cn);
                }
                *reinterpret_cast<float2*>(out + row * 512 + j) =
                    make_float2(hv[0], hv[1]);
                *reinterpret_cast<float2*>(out + HC + row * 512 + j) =
                    make_float2(cv[0], cv[1]);
            }
        }
    }
}

extern "C" void kernel_launch(void* const* d_in, const int* in_sizes, int n_in,
                              void* d_out, int out_size) {
    const float* x  = (const float*)d_in[0];
    const float* h  = (const float*)d_in[1];
    const float* c  = (const float*)d_in[2];
    const float* Wx = (const float*)d_in[3];
    const float* Wh = (const float*)d_in[4];
    const float* bx = (const float*)d_in[5];
    const float* bh = (const float*)d_in[6];
    float* out = (float*)d_out;

    static bool attr_set = false;
    if (!attr_set) {
        cudaFuncSetAttribute(lstm_mma,
                             cudaFuncAttributeMaxDynamicSharedMemorySize,
                             SMEM_BYTES);
        attr_set = true;
    }

    {   // prepass 1: x,h -> fp16 concatenated A
        size_t nthr = (size_t)Bsz * INF / 4 * 2;     // 4M threads
        prep_A<<<(unsigned)((nthr + 255) / 256), 256>>>(x, h);
    }
    prep_Bt<<<dim3(Ktot / 32, FH / 32), dim3(32, 8)>>>(Wx, Wh);
    lstm_mma<<<dim3(FH / BN, Bsz / BM), 256, SMEM_BYTES>>>(c, bx, bh, out);
}

// round 7
// speedup vs baseline: 5.2683x; 1.0456x over previous
#include <cuda_runtime.h>
#include <cuda_fp16.h>
#include <cstdint>

// LSTM cell: gates = [x|h] @ [Wx;Wh] + bx + bh, fused epilogue.
// B=16384, IN=H=512, K=1024, N=4H=2048.
// Round 7: fp16 mma m16n8k16 + ldmatrix, BK=64, frag double-buffering.
// Changes vs R6: single merged prepass (A-convert MLP=4 + W-transpose),
// removed redundant bottom __syncthreads in the mainloop.

static constexpr int Bsz  = 16384;
static constexpr int INF  = 512;
static constexpr int Hd   = 512;
static constexpr int FH   = 2048;
static constexpr int Ktot = 1024;

#define BM 128
#define BN 256
#define BK 64
#define NSTAGE 3
#define NITER (Ktot / BK)              // 16
#define ROWSTR 72                      // halves per SMEM row (144 B)
#define A_STG_B (BM * ROWSTR * 2)      // 18432 B
#define B_STG_B (BN * ROWSTR * 2)      // 36864 B
#define STG_B   (A_STG_B + B_STG_B)    // 55296 B
#define SMEM_BYTES (1024 + NSTAGE * STG_B)   // 166912

// prepass grid split
#define PREP_A_BLKS 4096               // 4096 blk * 256 thr * 4 float4 = 4M float4
#define PREP_W_BLKS (32 * 64)          // (Ktot/32) * (FH/32)
#define PREP_BLKS   (PREP_A_BLKS + PREP_W_BLKS)

__device__ __half g_A16[(size_t)Bsz * Ktot];   // 32 MB  [b][k]  (x | h)
__device__ __half g_Bt16[(size_t)FH * Ktot];   // 4 MB   [n'][k] gate-interleaved

// ---------------- helpers ----------------
__device__ __forceinline__ uint32_t cvta_s(const void* p) {
    return (uint32_t)__cvta_generic_to_shared(p);
}
__device__ __forceinline__ void cpa16(uint32_t s, const void* g) {
    asm volatile("cp.async.cg.shared.global [%0], [%1], 16;"
                 :: "r"(s), "l"(g) : "memory");
}
__device__ __forceinline__ void ldm4(uint32_t* r, uint32_t a) {
    asm volatile("ldmatrix.sync.aligned.m8n8.x4.shared.b16 {%0,%1,%2,%3}, [%4];"
                 : "=r"(r[0]), "=r"(r[1]), "=r"(r[2]), "=r"(r[3]) : "r"(a));
}
__device__ __forceinline__ void mma16(float* d, const uint32_t* a, const uint32_t* b) {
    asm volatile(
        "mma.sync.aligned.m16n8k16.row.col.f32.f16.f16.f32 "
        "{%0,%1,%2,%3}, {%4,%5,%6,%7}, {%8,%9}, {%0,%1,%2,%3};"
        : "+f"(d[0]), "+f"(d[1]), "+f"(d[2]), "+f"(d[3])
        : "r"(a[0]), "r"(a[1]), "r"(a[2]), "r"(a[3]), "r"(b[0]), "r"(b[1]));
}
__device__ __forceinline__ float rcp_(float a) {
    float r; asm("rcp.approx.f32 %0, %1;" : "=f"(r) : "f"(a)); return r;
}
__device__ __forceinline__ float sigm_(float v) { return rcp_(1.0f + __expf(-v)); }
__device__ __forceinline__ float tanh_(float v) {
    return 2.0f * rcp_(1.0f + __expf(-2.0f * v)) - 1.0f;
}
__device__ __forceinline__ uint2 pack4h(float a, float b, float cc, float d) {
    union { __half2 h2[2]; uint2 u; } u;
    u.h2[0] = __floats2half2_rn(a, b);
    u.h2[1] = __floats2half2_rn(cc, d);
    return u.u;
}

// ---------------- merged prepass ----------------
// blocks [0, PREP_A_BLKS): convert x|h -> g_A16 (4 independent float4/thread)
// blocks [PREP_A_BLKS, ...): 32x32 W transpose tile -> g_Bt16 (gate-interleaved)
__global__ void prep_all(const float* __restrict__ x, const float* __restrict__ h,
                         const float* __restrict__ Wx, const float* __restrict__ Wh)
{
    if (blockIdx.x < PREP_A_BLKS) {
        const size_t t = (size_t)blockIdx.x * 256 + threadIdx.x;   // 1M threads
        const size_t NQ = (size_t)Bsz * INF / 4;                   // 2M float4/stream
        const size_t S  = NQ / 2;                                  // 1M stride
        // 4 independent loads (2 from x, 2 from h) -> MLP 4
        float4 vx0 = *reinterpret_cast<const float4*>(x + (t)      * 4);
        float4 vx1 = *reinterpret_cast<const float4*>(x + (t + S)  * 4);
        float4 vh0 = *reinterpret_cast<const float4*>(h + (t)      * 4);
        float4 vh1 = *reinterpret_cast<const float4*>(h + (t + S)  * 4);
        {   size_t b = t >> 7, c4 = (t & 127) * 4;
            *reinterpret_cast<uint2*>(g_A16 + b * Ktot + c4) =
                pack4h(vx0.x, vx0.y, vx0.z, vx0.w); }
        {   size_t q = t + S; size_t b = q >> 7, c4 = (q & 127) * 4;
            *reinterpret_cast<uint2*>(g_A16 + b * Ktot + c4) =
                pack4h(vx1.x, vx1.y, vx1.z, vx1.w); }
        {   size_t b = t >> 7, c4 = (t & 127) * 4;
            *reinterpret_cast<uint2*>(g_A16 + b * Ktot + 512 + c4) =
                pack4h(vh0.x, vh0.y, vh0.z, vh0.w); }
        {   size_t q = t + S; size_t b = q >> 7, c4 = (q & 127) * 4;
            *reinterpret_cast<uint2*>(g_A16 + b * Ktot + 512 + c4) =
                pack4h(vh1.x, vh1.y, vh1.z, vh1.w); }
        return;
    }

    // ---- W transpose part ----
    __shared__ float t[32][33];
    const int wb = blockIdx.x - PREP_A_BLKS;
    const int k0 = (wb & 31) * 32;                  // Ktot/32 = 32
    const int n0 = (wb >> 5) * 32;                  // FH/32 = 64
    const float* W = (k0 < INF) ? (Wx + (size_t)k0 * FH)
                                : (Wh + (size_t)(k0 - INF) * FH);
    const int tx = threadIdx.x & 31, ty = threadIdx.x >> 5;   // 32 x 8
    #pragma unroll
    for (int i = 0; i < 4; ++i) {
        int kk = ty + i * 8;
        t[kk][tx] = W[(size_t)kk * FH + n0 + tx];
    }
    __syncthreads();
    const int gate = n0 >> 9;
    const int j0   = n0 & 511;
    #pragma unroll
    for (int i = 0; i < 4; ++i) {
        int nn = ty + i * 8;
        int j  = j0 + nn;
        int np = ((j >> 4) << 6) + gate * 16 + (j & 15);
        g_Bt16[(size_t)np * Ktot + k0 + tx] = __float2half_rn(t[tx][nn]);
    }
}

// ---------------- main GEMM + LSTM epilogue ----------------
__global__ __launch_bounds__(256, 1)
void lstm_mma(const float* __restrict__ c,
              const float* __restrict__ bx, const float* __restrict__ bh,
              float* __restrict__ out)
{
    extern __shared__ char smraw[];
    float* biasS = reinterpret_cast<float*>(smraw);        // 256 floats
    char*  stg0  = smraw + 1024;

    const int tid  = threadIdx.x;
    const int lane = tid & 31;
    const int wid  = tid >> 5;
    const int wm   = wid >> 2;              // 0..1
    const int wn   = wid & 3;               // 0..3
    const int m0   = blockIdx.y * BM;
    const int n0   = blockIdx.x * BN;
    const int jb   = blockIdx.x * 64;

    {   // bias = bx + bh, gate-major [gate][64 j]
        int g = tid >> 6, jj = tid & 63;
        int colg = g * 512 + jb + jj;
        biasS[tid] = bx[colg] + bh[colg];
    }

    float acc[4][8][4];
    #pragma unroll
    for (int a = 0; a < 4; ++a)
        #pragma unroll
        for (int b = 0; b < 8; ++b)
            #pragma unroll
            for (int d = 0; d < 4; ++d) acc[a][b][d] = 0.0f;

    // ldmatrix per-lane geometry
    const int grp = lane >> 3, gi = lane & 7;
    const int a_row  = wm * 64 + (grp & 1) * 8 + gi;
    const int a_kofs = (grp >> 1) * 8;
    const uint32_t a_base = (uint32_t)(a_row * ROWSTR + a_kofs) * 2;
    const int b_row  = wn * 64 + (grp >> 1) * 8 + gi;
    const int b_kofs = (grp & 1) * 8;
    const uint32_t b_base = (uint32_t)(b_row * ROWSTR + b_kofs) * 2;

    auto load_stage = [&](int s, int kc) {
        const int k0 = kc * BK;
        char* As = stg0 + s * STG_B;
        char* Bs = As + A_STG_B;
        const __half* Ap = g_A16 + (size_t)m0 * Ktot + k0;
        #pragma unroll
        for (int p = 0; p < 4; ++p) {
            int q = tid + 256 * p, row = q >> 3, c8 = (q & 7) * 8;
            cpa16(cvta_s(As + (row * ROWSTR + c8) * 2),
                  Ap + (size_t)row * Ktot + c8);
        }
        const __half* Bp = g_Bt16 + (size_t)n0 * Ktot + k0;
        #pragma unroll
        for (int p = 0; p < 8; ++p) {
            int q = tid + 256 * p, row = q >> 3, c8 = (q & 7) * 8;
            cpa16(cvta_s(Bs + (row * ROWSTR + c8) * 2),
                  Bp + (size_t)row * Ktot + c8);
        }
        asm volatile("cp.async.commit_group;" ::: "memory");
    };

    load_stage(0, 0);
    load_stage(1, 1);

    uint32_t afr[2][4][4], bfr[2][4][4];

    for (int it = 0; it < NITER; ++it) {
        asm volatile("cp.async.wait_group 1;" ::: "memory");
        // This single barrier both publishes stage `it` to all warps and
        // guarantees everyone is done reading the stage about to be
        // overwritten by load_stage below (written at it-1's compute).
        __syncthreads();
        if (it + 2 < NITER) load_stage((it + 2) % NSTAGE, it + 2);
        else asm volatile("cp.async.commit_group;" ::: "memory");

        const uint32_t sA = cvta_s(stg0 + (it % NSTAGE) * STG_B);
        const uint32_t sB = sA + A_STG_B;

        // preload fragments for ks=0
        #pragma unroll
        for (int mf = 0; mf < 4; ++mf)
            ldm4(afr[0][mf], sA + a_base + mf * (16 * ROWSTR * 2));
        #pragma unroll
        for (int np = 0; np < 4; ++np)
            ldm4(bfr[0][np], sB + b_base + np * (16 * ROWSTR * 2));

        #pragma unroll
        for (int ks = 0; ks < 4; ++ks) {             // four k16 steps per stage
            const int cur = ks & 1;
            if (ks < 3) {                            // prefetch next k16 frags
                const int nxt = cur ^ 1;
                #pragma unroll
                for (int mf = 0; mf < 4; ++mf)
                    ldm4(afr[nxt][mf],
                         sA + a_base + mf * (16 * ROWSTR * 2) + (ks + 1) * 32);
                #pragma unroll
                for (int np = 0; np < 4; ++np)
                    ldm4(bfr[nxt][np],
                         sB + b_base + np * (16 * ROWSTR * 2) + (ks + 1) * 32);
            }
            #pragma unroll
            for (int mf = 0; mf < 4; ++mf)
                #pragma unroll
                for (int np = 0; np < 4; ++np) {
                    mma16(acc[mf][np * 2 + 0], afr[cur][mf], &bfr[cur][np][0]);
                    mma16(acc[mf][np * 2 + 1], afr[cur][mf], &bfr[cur][np][2]);
                }
        }
        // no bottom barrier: next iteration's top barrier provides the guard
    }

    // ---- fused LSTM epilogue (thread-local: all 4 gates per j) ----
    const size_t HC = (size_t)Bsz * Hd;
    #pragma unroll
    for (int mf = 0; mf < 4; ++mf) {
        #pragma unroll
        for (int e = 0; e < 2; ++e) {
            size_t row = (size_t)m0 + wm * 64 + mf * 16 + (lane >> 2) + e * 8;
            #pragma unroll
            for (int half = 0; half < 2; ++half) {
                int q  = 2 * (lane & 3) + half * 8;   // j within warp's 16
                int bq = wn * 16 + q;                 // j within CTA's 64
                int j  = jb + bq;
                float2 cold = *reinterpret_cast<const float2*>(c + row * 512 + j);
                float hv[2], cv[2];
                #pragma unroll
                for (int d = 0; d < 2; ++d) {
                    float gi = acc[mf][0 + half][e * 2 + d] + biasS[      bq + d];
                    float gf = acc[mf][2 + half][e * 2 + d] + biasS[ 64 + bq + d];
                    float gg = acc[mf][4 + half][e * 2 + d] + biasS[128 + bq + d];
                    float go = acc[mf][6 + half][e * 2 + d] + biasS[192 + bq + d];
                    float i_ = sigm_(gi), f_ = sigm_(gf);
                    float g_ = tanh_(gg), o_ = sigm_(go);
                    float co = d ? cold.y : cold.x;
                    float cn = f_ * co + i_ * g_;
                    cv[d] = cn;
                    hv[d] = o_ * tanh_(cn);
                }
                *reinterpret_cast<float2*>(out + row * 512 + j) =
                    make_float2(hv[0], hv[1]);
                *reinterpret_cast<float2*>(out + HC + row * 512 + j) =
                    make_float2(cv[0], cv[1]);
            }
        }
    }
}

extern "C" void kernel_launch(void* const* d_in, const int* in_sizes, int n_in,
                              void* d_out, int out_size) {
    const float* x  = (const float*)d_in[0];
    const float* h  = (const float*)d_in[1];
    const float* c  = (const float*)d_in[2];
    const float* Wx = (const float*)d_in[3];
    const float* Wh = (const float*)d_in[4];
    const float* bx = (const float*)d_in[5];
    const float* bh = (const float*)d_in[6];
    float* out = (float*)d_out;

    static bool attr_set = false;
    if (!attr_set) {
        cudaFuncSetAttribute(lstm_mma,
                             cudaFuncAttributeMaxDynamicSharedMemorySize,
                             SMEM_BYTES);
        attr_set = true;
    }

    prep_all<<<PREP_BLKS, 256>>>(x, h, Wx, Wh);
    lstm_mma<<<dim3(FH / BN, Bsz / BM), 256, SMEM_BYTES>>>(c, bx, bh, out);
}